// round 2
// baseline (speedup 1.0000x reference)
#include <cuda_runtime.h>
#include <cuda_bf16.h>
#include <math.h>

// ---------------- problem constants ----------------
#define S 4096
#define HID 128
#define NHEADS 4
#define HD 32
#define NCOE 50
#define NSCALES 4

// ---------------- scratch (__device__ globals; no allocs allowed) ----------------
__device__ float  g_eig [S * HID];
__device__ float  g_tmp [S * HID];
__device__ float  g_qkv [S * 3 * HID];
__device__ float  g_att [S * HID];
__device__ float  g_h1  [S * HID];
__device__ float  g_eigf[S * HID];
__device__ double g_xsum[HID];
__device__ float  g_coef[128];   // [0:50) scaling, [50:100) wavelet, [100:104) scales

// ============================================================================
// K1: sine encoding + GEMM  ->  g_eig = eeig[S,129] @ W[129,128] + b
// block = 16 rows, 128 threads (one output column per thread)
// ============================================================================
__global__ void __launch_bounds__(128) k_sine_enc(const float* __restrict__ eve,
                                                  const float* __restrict__ W,
                                                  const float* __restrict__ b) {
    __shared__ float ee[16][132];   // 129 used
    const int m0  = blockIdx.x * 16;
    const int tid = threadIdx.x;
    const float kLog = -9.210340371976184f / 128.0f;   // -ln(1e4)/128

    for (int idx = tid; idx < 16 * 129; idx += 128) {
        int r = idx / 129, j = idx - r * 129;
        float e = eve[m0 + r];
        float val;
        if (j == 0) {
            val = e;
        } else if (j <= 64) {
            int i = j - 1;
            float div = __expf((2.0f * i) * kLog);
            val = sinf(e * 100.0f * div);
        } else {
            int i = j - 65;
            float div = __expf((2.0f * i) * kLog);
            val = cosf(e * 100.0f * div);
        }
        ee[r][j] = val;
    }
    __syncthreads();

    float acc[16];
#pragma unroll
    for (int r = 0; r < 16; r++) acc[r] = 0.0f;

    for (int k = 0; k < 129; k++) {
        float wv = W[k * HID + tid];
#pragma unroll
        for (int r = 0; r < 16; r++) acc[r] = fmaf(ee[r][k], wv, acc[r]);
    }
    float bb = b[tid];
#pragma unroll
    for (int r = 0; r < 16; r++) g_eig[(m0 + r) * HID + tid] = acc[r] + bb;
}

// ============================================================================
// K2: LayerNorm (one row per block, 128 threads)
// ============================================================================
__global__ void __launch_bounds__(128) k_ln(const float* __restrict__ X,
                                            const float* __restrict__ g,
                                            const float* __restrict__ b,
                                            float* __restrict__ Y) {
    const int row = blockIdx.x;
    const int tid = threadIdx.x;
    float x = X[row * HID + tid];
    __shared__ float red[4];

    float v = x;
#pragma unroll
    for (int o = 16; o; o >>= 1) v += __shfl_xor_sync(0xffffffffu, v, o);
    if ((tid & 31) == 0) red[tid >> 5] = v;
    __syncthreads();
    float mean = (red[0] + red[1] + red[2] + red[3]) * (1.0f / HID);
    __syncthreads();

    float d = x - mean;
    v = d * d;
#pragma unroll
    for (int o = 16; o; o >>= 1) v += __shfl_xor_sync(0xffffffffu, v, o);
    if ((tid & 31) == 0) red[tid >> 5] = v;
    __syncthreads();
    float var = (red[0] + red[1] + red[2] + red[3]) * (1.0f / HID);

    Y[row * HID + tid] = d * rsqrtf(var + 1e-5f) * g[tid] + b[tid];
}

// ============================================================================
// K3/K5/K7/K8: GEMM  C[M,N] = act(A[M,128] @ W[128,N] + bias) (+ R)
// 16 rows per block, 128 threads. NC = N/128 columns per thread.
// ACT: 0 = none, 1 = exact gelu. RESID only valid for N==128.
// ============================================================================
template <int NC, int ACT, int RESID>
__global__ void __launch_bounds__(128) k_gemm(const float* __restrict__ A,
                                              const float* __restrict__ W,
                                              const float* __restrict__ bias,
                                              const float* __restrict__ R,
                                              float* __restrict__ C) {
    constexpr int N = NC * 128;
    __shared__ float As[16][HID];
    const int m0  = blockIdx.x * 16;
    const int tid = threadIdx.x;

    for (int idx = tid; idx < 16 * HID; idx += 128)
        As[idx >> 7][idx & 127] = A[m0 * HID + idx];
    __syncthreads();

    float acc[NC][16];
#pragma unroll
    for (int c = 0; c < NC; c++)
#pragma unroll
        for (int r = 0; r < 16; r++) acc[c][r] = 0.0f;

    for (int k = 0; k < HID; k += 4) {
        float wv[4][NC];
#pragma unroll
        for (int i = 0; i < 4; i++)
#pragma unroll
            for (int c = 0; c < NC; c++)
                wv[i][c] = W[(k + i) * N + c * 128 + tid];
#pragma unroll
        for (int r = 0; r < 16; r++) {
            float4 a4 = *reinterpret_cast<const float4*>(&As[r][k]);
#pragma unroll
            for (int c = 0; c < NC; c++) {
                acc[c][r] = fmaf(a4.x, wv[0][c], acc[c][r]);
                acc[c][r] = fmaf(a4.y, wv[1][c], acc[c][r]);
                acc[c][r] = fmaf(a4.z, wv[2][c], acc[c][r]);
                acc[c][r] = fmaf(a4.w, wv[3][c], acc[c][r]);
            }
        }
    }

#pragma unroll
    for (int c = 0; c < NC; c++) {
        int col = c * 128 + tid;
        float bb = bias[col];
#pragma unroll
        for (int r = 0; r < 16; r++) {
            float v = acc[c][r] + bb;
            if (ACT == 1) v = 0.5f * v * (1.0f + erff(v * 0.70710678118654752f));
            if (RESID)    v += R[(m0 + r) * HID + tid];
            C[(m0 + r) * N + col] = v;
        }
    }
}

// ============================================================================
// K4: flash attention, fp32 SIMT. grid = (32 qblocks, 4 heads), 128 threads.
// One query per thread; 32-key smem tiles for K and V.
// ============================================================================
__global__ void __launch_bounds__(128) k_attn(const float* __restrict__ qkv,
                                              const int* __restrict__ snp) {
    const int h   = blockIdx.y;
    const int tid = threadIdx.x;
    const int q   = blockIdx.x * 128 + tid;
    const int sn  = *snp;
    const float scale = 0.17677669529663687f;   // 1/sqrt(32)

    float qr[HD];
#pragma unroll
    for (int d = 0; d < HD; d++) qr[d] = qkv[q * 384 + h * HD + d] * scale;

    float m = -INFINITY, l = 0.0f;
    float o[HD];
#pragma unroll
    for (int d = 0; d < HD; d++) o[d] = 0.0f;

    __shared__ float Ks[32][HD];
    __shared__ float Vs[32][HD];

    for (int kb = 0; kb < S; kb += 32) {
        __syncthreads();
        for (int idx = tid; idx < 32 * HD; idx += 128) {
            int j = idx >> 5, d = idx & 31;
            Ks[j][d] = qkv[(kb + j) * 384 + 128 + h * HD + d];
            Vs[j][d] = qkv[(kb + j) * 384 + 256 + h * HD + d];
        }
        __syncthreads();

        float s[32];
#pragma unroll
        for (int j = 0; j < 32; j++) {
            const float4* kp = reinterpret_cast<const float4*>(Ks[j]);
            float a = 0.0f;
#pragma unroll
            for (int d4 = 0; d4 < 8; d4++) {
                float4 kv = kp[d4];
                a = fmaf(qr[d4 * 4 + 0], kv.x, a);
                a = fmaf(qr[d4 * 4 + 1], kv.y, a);
                a = fmaf(qr[d4 * 4 + 2], kv.z, a);
                a = fmaf(qr[d4 * 4 + 3], kv.w, a);
            }
            s[j] = (kb + j < sn) ? a : -INFINITY;
        }

        float mt = m;
#pragma unroll
        for (int j = 0; j < 32; j++) mt = fmaxf(mt, s[j]);
        float corr = __expf(m - mt);
        l *= corr;
#pragma unroll
        for (int d = 0; d < HD; d++) o[d] *= corr;

#pragma unroll
        for (int j = 0; j < 32; j++) {
            float p = __expf(s[j] - mt);
            l += p;
            const float4* vp = reinterpret_cast<const float4*>(Vs[j]);
#pragma unroll
            for (int d4 = 0; d4 < 8; d4++) {
                float4 vv = vp[d4];
                o[d4 * 4 + 0] = fmaf(p, vv.x, o[d4 * 4 + 0]);
                o[d4 * 4 + 1] = fmaf(p, vv.y, o[d4 * 4 + 1]);
                o[d4 * 4 + 2] = fmaf(p, vv.z, o[d4 * 4 + 2]);
                o[d4 * 4 + 3] = fmaf(p, vv.w, o[d4 * 4 + 3]);
            }
        }
        m = mt;
    }

    float inv = 1.0f / l;
#pragma unroll
    for (int d = 0; d < HD; d++)
        g_att[q * HID + h * HD + d] = o[d] * inv;
}

// ============================================================================
// K9a/K9b: masked row-sum of eig_filter (double accumulation)
// ============================================================================
__global__ void k_zero_xsum() {
    g_xsum[threadIdx.x] = 0.0;
}

__global__ void __launch_bounds__(128) k_rowsum(const int* __restrict__ snp) {
    const int sn  = *snp;
    const int tid = threadIdx.x;
    const int m0  = blockIdx.x * 128;
    double acc = 0.0;
    for (int r = 0; r < 128; r++) {
        int row = m0 + r;
        if (row < sn) acc += (double)g_eigf[row * HID + tid];
    }
    atomicAdd(&g_xsum[tid], acc);
}

// ============================================================================
// K10: pooled coefficients (single block)
// pooled_c = (xsum . W[:,c] + sn*b_c) / (len + 1e-8); sigmoid; normalize / *THRE
// ============================================================================
__global__ void __launch_bounds__(128) k_pool(const float* __restrict__ dscW, const float* __restrict__ dscb,
                                              const float* __restrict__ dwvW, const float* __restrict__ dwvb,
                                              const float* __restrict__ dssW, const float* __restrict__ dssb,
                                              const int* __restrict__ lenp, const int* __restrict__ snp) {
    const int tid = threadIdx.x;
    __shared__ float sig[104];
    __shared__ float ssum[2];
    const float lenf = (float)(*lenp);
    const float snf  = (float)(*snp);

    if (tid < 104) {
        const float* W; const float* bb; int c; int NCc;
        if (tid < 50)       { W = dscW; bb = dscb; c = tid;       NCc = NCOE; }
        else if (tid < 100) { W = dwvW; bb = dwvb; c = tid - 50;  NCc = NCOE; }
        else                { W = dssW; bb = dssb; c = tid - 100; NCc = NSCALES; }
        double acc = 0.0;
        for (int k = 0; k < HID; k++) acc += g_xsum[k] * (double)W[k * NCc + c];
        float pooled = (float)((acc + (double)(snf * bb[c])) / (double)(lenf + 1e-8f));
        sig[tid] = 1.0f / (1.0f + expf(-pooled));
    }
    __syncthreads();
    if (tid == 0) { float t = 0.f; for (int i = 0;  i < 50;  i++) t += sig[i]; ssum[0] = t; }
    if (tid == 1) { float t = 0.f; for (int i = 50; i < 100; i++) t += sig[i]; ssum[1] = t; }
    __syncthreads();
    if (tid < 50)       g_coef[tid] = sig[tid] / (ssum[0] + 1e-8f);
    else if (tid < 100) g_coef[tid] = sig[tid] / (ssum[1] + 1e-8f);
    else if (tid < 104) g_coef[tid] = sig[tid] * 5.0f;   // THRE
}

// ============================================================================
// K11: Chebyshev synthesis + L2 normalize  ->  out[S, 5]
// scaling basis = T_1,T_3,...,T_99 ; wavelet basis = T_0,T_2,...,T_98
// ============================================================================
__global__ void __launch_bounds__(128) k_final(const float* __restrict__ eve,
                                               float* __restrict__ out) {
    __shared__ float cs[NCOE], cw[NCOE], sc[NSCALES];
    const int tid = threadIdx.x;
    if (tid < 50)        cs[tid]       = g_coef[tid];
    else if (tid < 100)  cw[tid - 50]  = g_coef[tid];
    else if (tid < 104)  sc[tid - 100] = g_coef[tid];
    __syncthreads();

    const int s = blockIdx.x * 128 + tid;
    const float e = eve[s];
    float vals[5];

    {   // scaling channel: y = e - 1
        float y  = e - 1.0f;
        float te = 1.0f, to = y;
        float acc = cs[0] * (0.5f * (1.0f - to));
#pragma unroll
        for (int c = 1; c < NCOE; c++) {
            te = 2.0f * y * to - te;          // T_{2c}
            to = 2.0f * y * te - to;          // T_{2c+1}
            acc += cs[c] * (0.5f * (1.0f - to));
        }
        vals[0] = acc;
    }

#pragma unroll
    for (int j = 0; j < NSCALES; j++) {       // wavelet channels
        float f = e * sc[j];
        if (f > 2.0f) f = 0.0f;
        float y  = f - 1.0f;
        float te = 1.0f, to = y;
        float acc = 0.0f;                      // cw[0] * 0.5*(1-T_0) = 0
#pragma unroll
        for (int c = 1; c < NCOE; c++) {
            te = 2.0f * y * to - te;          // T_{2c}
            acc += cw[c] * (0.5f * (1.0f - te));
            to = 2.0f * y * te - to;          // T_{2c+1}
        }
        vals[1 + j] = acc;
    }

    float n2 = 0.0f;
#pragma unroll
    for (int i = 0; i < 5; i++) n2 += vals[i] * vals[i];
    float inv = 1.0f / (sqrtf(n2) + 1e-8f);
#pragma unroll
    for (int i = 0; i < 5; i++) out[s * 5 + i] = vals[i] * inv;
}

// ============================================================================
// launch
// ============================================================================
extern "C" void kernel_launch(void* const* d_in, const int* in_sizes, int n_in,
                              void* d_out, int out_size) {
    const float* eve      = (const float*)d_in[0];
    const int*   lenp     = (const int*)  d_in[1];
    const int*   snp      = (const int*)  d_in[2];
    const float* eig_w_W  = (const float*)d_in[3];
    const float* eig_w_b  = (const float*)d_in[4];
    const float* mha_ln_g = (const float*)d_in[5];
    const float* mha_ln_b = (const float*)d_in[6];
    const float* in_W     = (const float*)d_in[7];
    const float* in_b     = (const float*)d_in[8];
    const float* out_W    = (const float*)d_in[9];
    const float* out_b    = (const float*)d_in[10];
    const float* ffn_ln_g = (const float*)d_in[11];
    const float* ffn_ln_b = (const float*)d_in[12];
    const float* ffn1_W   = (const float*)d_in[13];
    const float* ffn1_b   = (const float*)d_in[14];
    const float* ffn2_W   = (const float*)d_in[15];
    const float* ffn2_b   = (const float*)d_in[16];
    const float* dsc_W    = (const float*)d_in[17];
    const float* dsc_b    = (const float*)d_in[18];
    const float* dwv_W    = (const float*)d_in[19];
    const float* dwv_b    = (const float*)d_in[20];
    const float* dss_W    = (const float*)d_in[21];
    const float* dss_b    = (const float*)d_in[22];
    float* out = (float*)d_out;

    float *p_eig, *p_tmp, *p_qkv, *p_att, *p_h1, *p_eigf;
    cudaGetSymbolAddress((void**)&p_eig,  g_eig);
    cudaGetSymbolAddress((void**)&p_tmp,  g_tmp);
    cudaGetSymbolAddress((void**)&p_qkv,  g_qkv);
    cudaGetSymbolAddress((void**)&p_att,  g_att);
    cudaGetSymbolAddress((void**)&p_h1,   g_h1);
    cudaGetSymbolAddress((void**)&p_eigf, g_eigf);

    // 1) eig = sine_encoding(eve) @ W + b
    k_sine_enc<<<S / 16, 128>>>(eve, eig_w_W, eig_w_b);
    // 2) tmp = LN(eig)
    k_ln<<<S, 128>>>(p_eig, mha_ln_g, mha_ln_b, p_tmp);
    // 3) qkv = tmp @ in_W + in_b
    k_gemm<3, 0, 0><<<S / 16, 128>>>(p_tmp, in_W, in_b, nullptr, p_qkv);
    // 4) attention
    k_attn<<<dim3(S / 128, NHEADS), 128>>>(p_qkv, snp);
    // 5) eig = eig + att @ out_W + out_b
    k_gemm<1, 0, 1><<<S / 16, 128>>>(p_att, out_W, out_b, p_eig, p_eig);
    // 6) tmp = LN(eig)
    k_ln<<<S, 128>>>(p_eig, ffn_ln_g, ffn_ln_b, p_tmp);
    // 7) h1 = gelu(tmp @ ffn1_W + b)
    k_gemm<1, 1, 0><<<S / 16, 128>>>(p_tmp, ffn1_W, ffn1_b, nullptr, p_h1);
    // 8) eigf = eig + h1 @ ffn2_W + b
    k_gemm<1, 0, 1><<<S / 16, 128>>>(p_h1, ffn2_W, ffn2_b, p_eig, p_eigf);
    // 9) masked row-sum (double)
    k_zero_xsum<<<1, 128>>>();
    k_rowsum<<<S / 128, 128>>>(snp);
    // 10) pooled coefficients
    k_pool<<<1, 128>>>(dsc_W, dsc_b, dwv_W, dwv_b, dss_W, dss_b, lenp, snp);
    // 11) Chebyshev synthesis + normalize
    k_final<<<S / 128, 128>>>(eve, out);
}

// round 3
// speedup vs baseline: 1.7512x; 1.7512x over previous
#include <cuda_runtime.h>
#include <cuda_bf16.h>
#include <math.h>

// ---------------- problem constants ----------------
#define S 4096
#define HID 128
#define NHEADS 4
#define HD 32
#define NCOE 50
#define NSCALES 4
#define NK 16            // split-K chunks for attention
#define KCH (S / NK)     // 256 keys per chunk

// ---------------- scratch (__device__ globals; no allocs allowed) ----------------
__device__ float  g_eig [S * HID];
__device__ float  g_qkv [S * 3 * HID];
__device__ float  g_att [S * HID];
__device__ float  g_h1  [S * HID];
__device__ float  g_eigf[S * HID];
__device__ float  g_pm  [NHEADS * NK * S];        // partial max
__device__ float  g_pl  [NHEADS * NK * S];        // partial sum
__device__ float  g_po  [NHEADS * NK * S * HD];   // partial (unnormalized) out
__device__ double g_xsum[HID];
__device__ float  g_coef[128];   // [0:50) scaling, [50:100) wavelet, [100:104) scales

// ============================================================================
// K1: sine encoding + GEMM  ->  g_eig = eeig[S,129] @ W[129,128] + b
// ============================================================================
__global__ void __launch_bounds__(128) k_sine_enc(const float* __restrict__ eve,
                                                  const float* __restrict__ W,
                                                  const float* __restrict__ b) {
    __shared__ float ee[16][132];   // 129 used
    const int m0  = blockIdx.x * 16;
    const int tid = threadIdx.x;
    const float kLog = -9.210340371976184f / 128.0f;   // -ln(1e4)/128

    for (int idx = tid; idx < 16 * 129; idx += 128) {
        int r = idx / 129, j = idx - r * 129;
        float e = eve[m0 + r];
        float val;
        if (j == 0) {
            val = e;
        } else if (j <= 64) {
            int i = j - 1;
            float div = __expf((2.0f * i) * kLog);
            val = sinf(e * 100.0f * div);
        } else {
            int i = j - 65;
            float div = __expf((2.0f * i) * kLog);
            val = cosf(e * 100.0f * div);
        }
        ee[r][j] = val;
    }
    __syncthreads();

    float acc[16];
#pragma unroll
    for (int r = 0; r < 16; r++) acc[r] = 0.0f;

    for (int k = 0; k < 129; k++) {
        float wv = W[k * HID + tid];
#pragma unroll
        for (int r = 0; r < 16; r++) acc[r] = fmaf(ee[r][k], wv, acc[r]);
    }
    float bb = b[tid];
#pragma unroll
    for (int r = 0; r < 16; r++) g_eig[(m0 + r) * HID + tid] = acc[r] + bb;
}

// ============================================================================
// GEMM  C[M,N] = act( LN?(A)[M,128] @ W[128,N] + bias ) (+ R)
// 16 rows per block, 128 threads. NC = N/128 columns per thread.
// ACT: 0 = none, 1 = exact gelu. RESID: add R. LNORM: layernorm the A tile.
// ============================================================================
template <int NC, int ACT, int RESID, int LNORM>
__global__ void __launch_bounds__(128) k_gemm(const float* __restrict__ A,
                                              const float* __restrict__ W,
                                              const float* __restrict__ bias,
                                              const float* __restrict__ R,
                                              float* __restrict__ C,
                                              const float* __restrict__ lng,
                                              const float* __restrict__ lnb) {
    constexpr int N = NC * 128;
    __shared__ float As[16][HID];
    __shared__ float rowMean[16], rowRstd[16];
    const int m0  = blockIdx.x * 16;
    const int tid = threadIdx.x;

    for (int idx = tid; idx < 16 * HID; idx += 128)
        As[idx >> 7][idx & 127] = A[m0 * HID + idx];
    __syncthreads();

    if (LNORM) {
        // per-row mean/var: 8 threads per row, each sums 16 elems
        const int r = tid >> 3, l8 = tid & 7;
        float s = 0.0f, s2 = 0.0f;
        for (int j = l8; j < HID; j += 8) {
            float v = As[r][j];
            s += v; s2 += v * v;
        }
#pragma unroll
        for (int o = 4; o; o >>= 1) {
            s  += __shfl_xor_sync(0xffffffffu, s,  o);
            s2 += __shfl_xor_sync(0xffffffffu, s2, o);
        }
        if (l8 == 0) {
            float mean = s * (1.0f / HID);
            float var  = s2 * (1.0f / HID) - mean * mean;
            rowMean[r] = mean;
            rowRstd[r] = rsqrtf(var + 1e-5f);
        }
        __syncthreads();
        float gg = lng[tid], bb2 = lnb[tid];
#pragma unroll
        for (int r2 = 0; r2 < 16; r2++)
            As[r2][tid] = (As[r2][tid] - rowMean[r2]) * rowRstd[r2] * gg + bb2;
        __syncthreads();
    }

    float acc[NC][16];
#pragma unroll
    for (int c = 0; c < NC; c++)
#pragma unroll
        for (int r = 0; r < 16; r++) acc[c][r] = 0.0f;

    for (int k = 0; k < HID; k += 4) {
        float wv[4][NC];
#pragma unroll
        for (int i = 0; i < 4; i++)
#pragma unroll
            for (int c = 0; c < NC; c++)
                wv[i][c] = W[(k + i) * N + c * 128 + tid];
#pragma unroll
        for (int r = 0; r < 16; r++) {
            float4 a4 = *reinterpret_cast<const float4*>(&As[r][k]);
#pragma unroll
            for (int c = 0; c < NC; c++) {
                acc[c][r] = fmaf(a4.x, wv[0][c], acc[c][r]);
                acc[c][r] = fmaf(a4.y, wv[1][c], acc[c][r]);
                acc[c][r] = fmaf(a4.z, wv[2][c], acc[c][r]);
                acc[c][r] = fmaf(a4.w, wv[3][c], acc[c][r]);
            }
        }
    }

#pragma unroll
    for (int c = 0; c < NC; c++) {
        int col = c * 128 + tid;
        float bb = bias[col];
#pragma unroll
        for (int r = 0; r < 16; r++) {
            float v = acc[c][r] + bb;
            if (ACT == 1) v = 0.5f * v * (1.0f + erff(v * 0.70710678118654752f));
            if (RESID)    v += R[(m0 + r) * HID + tid];
            C[(m0 + r) * N + col] = v;
        }
    }
}

// ============================================================================
// K4a: split-K flash attention partial. grid = (32 qblocks, 4 heads, NK chunks)
// One query per thread; 32-key smem tiles. Writes unnormalized partials.
// ============================================================================
__global__ void __launch_bounds__(128) k_attn_part(const float* __restrict__ qkv,
                                                   const int* __restrict__ snp) {
    const int h   = blockIdx.y;
    const int kc  = blockIdx.z;
    const int tid = threadIdx.x;
    const int q   = blockIdx.x * 128 + tid;
    const int sn  = *snp;
    const float scale = 0.17677669529663687f;   // 1/sqrt(32)

    float qr[HD];
    {
        const float4* qp = reinterpret_cast<const float4*>(qkv + q * 384 + h * HD);
#pragma unroll
        for (int d4 = 0; d4 < 8; d4++) {
            float4 v = qp[d4];
            qr[d4 * 4 + 0] = v.x * scale;
            qr[d4 * 4 + 1] = v.y * scale;
            qr[d4 * 4 + 2] = v.z * scale;
            qr[d4 * 4 + 3] = v.w * scale;
        }
    }

    float m = -INFINITY, l = 0.0f;
    float o[HD];
#pragma unroll
    for (int d = 0; d < HD; d++) o[d] = 0.0f;

    __shared__ float Ks[32][HD];
    __shared__ float Vs[32][HD];

    const int kbeg = kc * KCH;
    const int jld  = tid >> 2;   // key index for staging (0..31)
    const int dld  = tid & 3;    // float4 slot (0..3; +4 second half)

    for (int kb = kbeg; kb < kbeg + KCH; kb += 32) {
        __syncthreads();
        {
            const float4* kp = reinterpret_cast<const float4*>(qkv + (kb + jld) * 384 + 128 + h * HD);
            const float4* vp = reinterpret_cast<const float4*>(qkv + (kb + jld) * 384 + 256 + h * HD);
            reinterpret_cast<float4*>(Ks[jld])[dld]     = kp[dld];
            reinterpret_cast<float4*>(Ks[jld])[dld + 4] = kp[dld + 4];
            reinterpret_cast<float4*>(Vs[jld])[dld]     = vp[dld];
            reinterpret_cast<float4*>(Vs[jld])[dld + 4] = vp[dld + 4];
        }
        __syncthreads();

        float s[32];
#pragma unroll
        for (int j = 0; j < 32; j++) {
            const float4* kp = reinterpret_cast<const float4*>(Ks[j]);
            float a = 0.0f;
#pragma unroll
            for (int d4 = 0; d4 < 8; d4++) {
                float4 kv = kp[d4];
                a = fmaf(qr[d4 * 4 + 0], kv.x, a);
                a = fmaf(qr[d4 * 4 + 1], kv.y, a);
                a = fmaf(qr[d4 * 4 + 2], kv.z, a);
                a = fmaf(qr[d4 * 4 + 3], kv.w, a);
            }
            s[j] = (kb + j < sn) ? a : -INFINITY;
        }

        float mt = m;
#pragma unroll
        for (int j = 0; j < 32; j++) mt = fmaxf(mt, s[j]);
        if (mt > -INFINITY) {
            float corr = (m > -INFINITY) ? __expf(m - mt) : 0.0f;
            l *= corr;
#pragma unroll
            for (int d = 0; d < HD; d++) o[d] *= corr;

#pragma unroll
            for (int j = 0; j < 32; j++) {
                float p = __expf(s[j] - mt);
                l += p;
                const float4* vp = reinterpret_cast<const float4*>(Vs[j]);
#pragma unroll
                for (int d4 = 0; d4 < 8; d4++) {
                    float4 vv = vp[d4];
                    o[d4 * 4 + 0] = fmaf(p, vv.x, o[d4 * 4 + 0]);
                    o[d4 * 4 + 1] = fmaf(p, vv.y, o[d4 * 4 + 1]);
                    o[d4 * 4 + 2] = fmaf(p, vv.z, o[d4 * 4 + 2]);
                    o[d4 * 4 + 3] = fmaf(p, vv.w, o[d4 * 4 + 3]);
                }
            }
            m = mt;
        }
    }

    const int p = (h * NK + kc) * S + q;
    g_pm[p] = m;
    g_pl[p] = l;
    float4* po = reinterpret_cast<float4*>(&g_po[(size_t)p * HD]);
#pragma unroll
    for (int d4 = 0; d4 < 8; d4++)
        po[d4] = make_float4(o[d4 * 4], o[d4 * 4 + 1], o[d4 * 4 + 2], o[d4 * 4 + 3]);
}

// ============================================================================
// K4b: split-K combine. grid = (S/128, 4 heads), 128 threads (1 query/thread)
// ============================================================================
__global__ void __launch_bounds__(128) k_attn_comb(void) {
    const int h   = blockIdx.y;
    const int q   = blockIdx.x * 128 + threadIdx.x;

    float M = -INFINITY;
#pragma unroll
    for (int kc = 0; kc < NK; kc++)
        M = fmaxf(M, g_pm[(h * NK + kc) * S + q]);

    float L = 0.0f;
    float o[HD];
#pragma unroll
    for (int d = 0; d < HD; d++) o[d] = 0.0f;

#pragma unroll
    for (int kc = 0; kc < NK; kc++) {
        const int p = (h * NK + kc) * S + q;
        float li = g_pl[p];
        if (li > 0.0f) {
            float w = __expf(g_pm[p] - M);
            L += li * w;
            const float4* po = reinterpret_cast<const float4*>(&g_po[(size_t)p * HD]);
#pragma unroll
            for (int d4 = 0; d4 < 8; d4++) {
                float4 v = po[d4];
                o[d4 * 4 + 0] = fmaf(w, v.x, o[d4 * 4 + 0]);
                o[d4 * 4 + 1] = fmaf(w, v.y, o[d4 * 4 + 1]);
                o[d4 * 4 + 2] = fmaf(w, v.z, o[d4 * 4 + 2]);
                o[d4 * 4 + 3] = fmaf(w, v.w, o[d4 * 4 + 3]);
            }
        }
    }

    float inv = (L > 0.0f) ? 1.0f / L : 0.0f;
#pragma unroll
    for (int d = 0; d < HD; d++)
        g_att[q * HID + h * HD + d] = o[d] * inv;
}

// ============================================================================
// masked row-sum of eig_filter (double accumulation)
// ============================================================================
__global__ void k_zero_xsum() {
    g_xsum[threadIdx.x] = 0.0;
}

__global__ void __launch_bounds__(128) k_rowsum(const int* __restrict__ snp) {
    const int sn  = *snp;
    const int tid = threadIdx.x;
    const int m0  = blockIdx.x * 128;
    double acc = 0.0;
    for (int r = 0; r < 128; r++) {
        int row = m0 + r;
        if (row < sn) acc += (double)g_eigf[row * HID + tid];
    }
    atomicAdd(&g_xsum[tid], acc);
}

// ============================================================================
// pooled coefficients (single block)
// ============================================================================
__global__ void __launch_bounds__(128) k_pool(const float* __restrict__ dscW, const float* __restrict__ dscb,
                                              const float* __restrict__ dwvW, const float* __restrict__ dwvb,
                                              const float* __restrict__ dssW, const float* __restrict__ dssb,
                                              const int* __restrict__ lenp, const int* __restrict__ snp) {
    const int tid = threadIdx.x;
    __shared__ float sig[104];
    __shared__ float ssum[2];
    const float lenf = (float)(*lenp);
    const float snf  = (float)(*snp);

    if (tid < 104) {
        const float* W; const float* bb; int c; int NCc;
        if (tid < 50)       { W = dscW; bb = dscb; c = tid;       NCc = NCOE; }
        else if (tid < 100) { W = dwvW; bb = dwvb; c = tid - 50;  NCc = NCOE; }
        else                { W = dssW; bb = dssb; c = tid - 100; NCc = NSCALES; }
        double acc = 0.0;
        for (int k = 0; k < HID; k++) acc += g_xsum[k] * (double)W[k * NCc + c];
        float pooled = (float)((acc + (double)(snf * bb[c])) / (double)(lenf + 1e-8f));
        sig[tid] = 1.0f / (1.0f + expf(-pooled));
    }
    __syncthreads();
    if (tid == 0) { float t = 0.f; for (int i = 0;  i < 50;  i++) t += sig[i]; ssum[0] = t; }
    if (tid == 1) { float t = 0.f; for (int i = 50; i < 100; i++) t += sig[i]; ssum[1] = t; }
    __syncthreads();
    if (tid < 50)       g_coef[tid] = sig[tid] / (ssum[0] + 1e-8f);
    else if (tid < 100) g_coef[tid] = sig[tid] / (ssum[1] + 1e-8f);
    else if (tid < 104) g_coef[tid] = sig[tid] * 5.0f;   // THRE
}

// ============================================================================
// Chebyshev synthesis + L2 normalize  ->  out[S, 5]
// ============================================================================
__global__ void __launch_bounds__(128) k_final(const float* __restrict__ eve,
                                               float* __restrict__ out) {
    __shared__ float cs[NCOE], cw[NCOE], sc[NSCALES];
    const int tid = threadIdx.x;
    if (tid < 50)        cs[tid]       = g_coef[tid];
    else if (tid < 100)  cw[tid - 50]  = g_coef[tid];
    else if (tid < 104)  sc[tid - 100] = g_coef[tid];
    __syncthreads();

    const int s = blockIdx.x * 128 + tid;
    const float e = eve[s];
    float vals[5];

    {   // scaling channel: y = e - 1; coefficients on T_1,T_3,...
        float y  = e - 1.0f;
        float te = 1.0f, to = y;
        float acc = cs[0] * (0.5f * (1.0f - to));
#pragma unroll
        for (int c = 1; c < NCOE; c++) {
            te = 2.0f * y * to - te;          // T_{2c}
            to = 2.0f * y * te - to;          // T_{2c+1}
            acc += cs[c] * (0.5f * (1.0f - to));
        }
        vals[0] = acc;
    }

#pragma unroll
    for (int j = 0; j < NSCALES; j++) {       // wavelet channels: T_0,T_2,...
        float f = e * sc[j];
        if (f > 2.0f) f = 0.0f;
        float y  = f - 1.0f;
        float te = 1.0f, to = y;
        float acc = 0.0f;                      // cw[0] * 0.5*(1-T_0) = 0
#pragma unroll
        for (int c = 1; c < NCOE; c++) {
            te = 2.0f * y * to - te;          // T_{2c}
            acc += cw[c] * (0.5f * (1.0f - te));
            to = 2.0f * y * te - to;          // T_{2c+1}
        }
        vals[1 + j] = acc;
    }

    float n2 = 0.0f;
#pragma unroll
    for (int i = 0; i < 5; i++) n2 += vals[i] * vals[i];
    float inv = 1.0f / (sqrtf(n2) + 1e-8f);
#pragma unroll
    for (int i = 0; i < 5; i++) out[s * 5 + i] = vals[i] * inv;
}

// ============================================================================
// launch
// ============================================================================
extern "C" void kernel_launch(void* const* d_in, const int* in_sizes, int n_in,
                              void* d_out, int out_size) {
    const float* eve      = (const float*)d_in[0];
    const int*   lenp     = (const int*)  d_in[1];
    const int*   snp      = (const int*)  d_in[2];
    const float* eig_w_W  = (const float*)d_in[3];
    const float* eig_w_b  = (const float*)d_in[4];
    const float* mha_ln_g = (const float*)d_in[5];
    const float* mha_ln_b = (const float*)d_in[6];
    const float* in_W     = (const float*)d_in[7];
    const float* in_b     = (const float*)d_in[8];
    const float* out_W    = (const float*)d_in[9];
    const float* out_b    = (const float*)d_in[10];
    const float* ffn_ln_g = (const float*)d_in[11];
    const float* ffn_ln_b = (const float*)d_in[12];
    const float* ffn1_W   = (const float*)d_in[13];
    const float* ffn1_b   = (const float*)d_in[14];
    const float* ffn2_W   = (const float*)d_in[15];
    const float* ffn2_b   = (const float*)d_in[16];
    const float* dsc_W    = (const float*)d_in[17];
    const float* dsc_b    = (const float*)d_in[18];
    const float* dwv_W    = (const float*)d_in[19];
    const float* dwv_b    = (const float*)d_in[20];
    const float* dss_W    = (const float*)d_in[21];
    const float* dss_b    = (const float*)d_in[22];
    float* out = (float*)d_out;

    float *p_eig, *p_qkv, *p_att, *p_h1, *p_eigf;
    cudaGetSymbolAddress((void**)&p_eig,  g_eig);
    cudaGetSymbolAddress((void**)&p_qkv,  g_qkv);
    cudaGetSymbolAddress((void**)&p_att,  g_att);
    cudaGetSymbolAddress((void**)&p_h1,   g_h1);
    cudaGetSymbolAddress((void**)&p_eigf, g_eigf);

    // 1) eig = sine_encoding(eve) @ W + b
    k_sine_enc<<<S / 16, 128>>>(eve, eig_w_W, eig_w_b);
    // 2) qkv = LN(eig) @ in_W + in_b        (LN fused)
    k_gemm<3, 0, 0, 1><<<S / 16, 128>>>(p_eig, in_W, in_b, nullptr, p_qkv, mha_ln_g, mha_ln_b);
    // 3) attention (split-K partials + combine)
    k_attn_part<<<dim3(S / 128, NHEADS, NK), 128>>>(p_qkv, snp);
    k_attn_comb<<<dim3(S / 128, NHEADS), 128>>>();
    // 4) eig = eig + att @ out_W + out_b
    k_gemm<1, 0, 1, 0><<<S / 16, 128>>>(p_att, out_W, out_b, p_eig, p_eig, nullptr, nullptr);
    // 5) h1 = gelu(LN(eig) @ ffn1_W + b)    (LN fused)
    k_gemm<1, 1, 0, 1><<<S / 16, 128>>>(p_eig, ffn1_W, ffn1_b, nullptr, p_h1, ffn_ln_g, ffn_ln_b);
    // 6) eigf = eig + h1 @ ffn2_W + b
    k_gemm<1, 0, 1, 0><<<S / 16, 128>>>(p_h1, ffn2_W, ffn2_b, p_eig, p_eigf, nullptr, nullptr);
    // 7) masked row-sum (double)
    k_zero_xsum<<<1, 128>>>();
    k_rowsum<<<S / 128, 128>>>(snp);
    // 8) pooled coefficients
    k_pool<<<1, 128>>>(dsc_W, dsc_b, dwv_W, dwv_b, dss_W, dss_b, lenp, snp);
    // 9) Chebyshev synthesis + normalize
    k_final<<<S / 128, 128>>>(eve, out);
}

// round 5
// speedup vs baseline: 3.1909x; 1.8221x over previous
#include <cuda_runtime.h>
#include <cuda_bf16.h>
#include <math.h>
#include <stdint.h>

// ---------------- problem constants ----------------
#define S 4096
#define HID 128
#define NHEADS 4
#define HD 32
#define NCOE 50
#define NSCALES 4
#define NKC 4              // split-K chunks for attention
#define CHUNK (S / NKC)    // 1024 keys per chunk
#define QT 128             // queries per block (8 warps x 16)
#define KT 64              // key tile

// ---------------- scratch (__device__ globals; no allocs allowed) ----------------
__device__ float  g_eig [S * HID];
__device__ float  g_qkv [S * 3 * HID];
__device__ float  g_att [S * HID];
__device__ float  g_h1  [S * HID];
__device__ float  g_eigf[S * HID];
__device__ float  g_pm  [NHEADS * NKC * S];        // partial max
__device__ float  g_pl  [NHEADS * NKC * S];        // partial sum
__device__ float  g_po  [NHEADS * NKC * S * HD];   // partial (unnormalized) out
__device__ double g_xsum[HID];
__device__ float  g_coef[128];   // [0:50) scaling, [50:100) wavelet, [100:104) scales

// ---------------- mma helpers ----------------
__device__ __forceinline__ void mma16816(float& c0, float& c1, float& c2, float& c3,
                                         uint32_t a0, uint32_t a1, uint32_t a2, uint32_t a3,
                                         uint32_t b0, uint32_t b1) {
    asm volatile("mma.sync.aligned.m16n8k16.row.col.f32.bf16.bf16.f32 "
                 "{%0,%1,%2,%3}, {%4,%5,%6,%7}, {%8,%9}, {%0,%1,%2,%3};\n"
                 : "+f"(c0), "+f"(c1), "+f"(c2), "+f"(c3)
                 : "r"(a0), "r"(a1), "r"(a2), "r"(a3), "r"(b0), "r"(b1));
}

__device__ __forceinline__ uint32_t packbf2(__nv_bfloat16 a, __nv_bfloat16 b) {
    __nv_bfloat162 t = __halves2bfloat162(a, b);   // a -> low half
    return *reinterpret_cast<uint32_t*>(&t);
}

// split x into hi (bf16) and lo (bf16 of remainder)
__device__ __forceinline__ void bsplit(float x, __nv_bfloat16& h, __nv_bfloat16& l) {
    h = __float2bfloat16(x);
    l = __float2bfloat16(x - __bfloat162float(h));
}

// pack two floats' hi parts and lo parts into bf16x2 regs
__device__ __forceinline__ void packsplit2(float x, float y, uint32_t& hi, uint32_t& lo) {
    __nv_bfloat16 xh, xl, yh, yl;
    bsplit(x, xh, xl);
    bsplit(y, yh, yl);
    hi = packbf2(xh, yh);
    lo = packbf2(xl, yl);
}

// ============================================================================
// K1: sine encoding + GEMM  ->  g_eig = eeig[S,129] @ W[129,128] + b
// ============================================================================
__global__ void __launch_bounds__(128) k_sine_enc(const float* __restrict__ eve,
                                                  const float* __restrict__ W,
                                                  const float* __restrict__ b) {
    __shared__ float ee[16][132];   // 129 used
    const int m0  = blockIdx.x * 16;
    const int tid = threadIdx.x;
    const float kLog = -9.210340371976184f / 128.0f;   // -ln(1e4)/128

    for (int idx = tid; idx < 16 * 129; idx += 128) {
        int r = idx / 129, j = idx - r * 129;
        float e = eve[m0 + r];
        float val;
        if (j == 0) {
            val = e;
        } else if (j <= 64) {
            int i = j - 1;
            float div = __expf((2.0f * i) * kLog);
            val = sinf(e * 100.0f * div);
        } else {
            int i = j - 65;
            float div = __expf((2.0f * i) * kLog);
            val = cosf(e * 100.0f * div);
        }
        ee[r][j] = val;
    }
    __syncthreads();

    float acc[16];
#pragma unroll
    for (int r = 0; r < 16; r++) acc[r] = 0.0f;

    for (int k = 0; k < 129; k++) {
        float wv = W[k * HID + tid];
#pragma unroll
        for (int r = 0; r < 16; r++) acc[r] = fmaf(ee[r][k], wv, acc[r]);
    }
    float bb = b[tid];
#pragma unroll
    for (int r = 0; r < 16; r++) g_eig[(m0 + r) * HID + tid] = acc[r] + bb;
}

// ============================================================================
// GEMM  C[M,N] = act( LN?(A)[M,128] @ W[128,N] + bias ) (+ R)
// ============================================================================
template <int NC, int ACT, int RESID, int LNORM>
__global__ void __launch_bounds__(128) k_gemm(const float* __restrict__ A,
                                              const float* __restrict__ W,
                                              const float* __restrict__ bias,
                                              const float* __restrict__ R,
                                              float* __restrict__ C,
                                              const float* __restrict__ lng,
                                              const float* __restrict__ lnb) {
    constexpr int N = NC * 128;
    __shared__ float As[16][HID];
    __shared__ float rowMean[16], rowRstd[16];
    const int m0  = blockIdx.x * 16;
    const int tid = threadIdx.x;

    for (int idx = tid; idx < 16 * HID; idx += 128)
        As[idx >> 7][idx & 127] = A[m0 * HID + idx];
    __syncthreads();

    if (LNORM) {
        const int r = tid >> 3, l8 = tid & 7;
        float s = 0.0f, s2 = 0.0f;
        for (int j = l8; j < HID; j += 8) {
            float v = As[r][j];
            s += v; s2 += v * v;
        }
#pragma unroll
        for (int o = 4; o; o >>= 1) {
            s  += __shfl_xor_sync(0xffffffffu, s,  o);
            s2 += __shfl_xor_sync(0xffffffffu, s2, o);
        }
        if (l8 == 0) {
            float mean = s * (1.0f / HID);
            float var  = s2 * (1.0f / HID) - mean * mean;
            rowMean[r] = mean;
            rowRstd[r] = rsqrtf(var + 1e-5f);
        }
        __syncthreads();
        float gg = lng[tid], bb2 = lnb[tid];
#pragma unroll
        for (int r2 = 0; r2 < 16; r2++)
            As[r2][tid] = (As[r2][tid] - rowMean[r2]) * rowRstd[r2] * gg + bb2;
        __syncthreads();
    }

    float acc[NC][16];
#pragma unroll
    for (int c = 0; c < NC; c++)
#pragma unroll
        for (int r = 0; r < 16; r++) acc[c][r] = 0.0f;

    for (int k = 0; k < HID; k += 4) {
        float wv[4][NC];
#pragma unroll
        for (int i = 0; i < 4; i++)
#pragma unroll
            for (int c = 0; c < NC; c++)
                wv[i][c] = W[(k + i) * N + c * 128 + tid];
#pragma unroll
        for (int r = 0; r < 16; r++) {
            float4 a4 = *reinterpret_cast<const float4*>(&As[r][k]);
#pragma unroll
            for (int c = 0; c < NC; c++) {
                acc[c][r] = fmaf(a4.x, wv[0][c], acc[c][r]);
                acc[c][r] = fmaf(a4.y, wv[1][c], acc[c][r]);
                acc[c][r] = fmaf(a4.z, wv[2][c], acc[c][r]);
                acc[c][r] = fmaf(a4.w, wv[3][c], acc[c][r]);
            }
        }
    }

#pragma unroll
    for (int c = 0; c < NC; c++) {
        int col = c * 128 + tid;
        float bb = bias[col];
#pragma unroll
        for (int r = 0; r < 16; r++) {
            float v = acc[c][r] + bb;
            if (ACT == 1) v = 0.5f * v * (1.0f + erff(v * 0.70710678118654752f));
            if (RESID)    v += R[(m0 + r) * HID + tid];
            C[(m0 + r) * N + col] = v;
        }
    }
}

// ============================================================================
// K4a: MMA flash attention partial (bf16x3 splits, fp32 accumulate).
// grid = (S/QT, NHEADS, NKC), block = 256 (8 warps x 16 queries).
// ============================================================================
__global__ void __launch_bounds__(256) k_attn_mma(const float* __restrict__ qkv,
                                                  const int* __restrict__ snp) {
    __shared__ __nv_bfloat16 Khi[KT][40], Klo[KT][40];     // [key][dim]
    __shared__ __nv_bfloat16 Vthi[HD][74], Vtlo[HD][74];   // [dim][key] (transposed)

    const int tid  = threadIdx.x;
    const int warp = tid >> 5;
    const int lane = tid & 31;
    const int g    = lane >> 2;    // group (row within fragment)
    const int t4   = lane & 3;     // thread-in-group
    const int h    = blockIdx.y;
    const int kc   = blockIdx.z;
    const int sn   = *snp;
    const float scale = 0.17677669529663687f;   // 1/sqrt(32)

    const int qbase = blockIdx.x * QT + warp * 16;
    const int r0 = qbase + g;        // query rows owned by this thread
    const int r1 = r0 + 8;

    // ---- load Q fragments (2 k-steps), split hi/lo ----
    uint32_t Qhi[2][4], Qlo[2][4];
#pragma unroll
    for (int ks = 0; ks < 2; ks++) {
#pragma unroll
        for (int hh = 0; hh < 2; hh++) {     // k-half (+0 / +8)
#pragma unroll
            for (int rr = 0; rr < 2; rr++) { // row g / g+8
                int row = rr ? r1 : r0;
                int d0  = ks * 16 + hh * 8 + 2 * t4;
                float x0 = qkv[row * 384 + h * HD + d0]     * scale;
                float x1 = qkv[row * 384 + h * HD + d0 + 1] * scale;
                int ri = hh * 2 + rr;
                packsplit2(x0, x1, Qhi[ks][ri], Qlo[ks][ri]);
            }
        }
    }

    float O[4][4];                    // [d-tile][frag] fp32 accumulators
#pragma unroll
    for (int nt = 0; nt < 4; nt++)
#pragma unroll
        for (int i = 0; i < 4; i++) O[nt][i] = 0.0f;
    float m0v = -INFINITY, m1v = -INFINITY, l0v = 0.0f, l1v = 0.0f;

    const int kbeg = kc * CHUNK;
    for (int kb = kbeg; kb < kbeg + CHUNK; kb += KT) {
        __syncthreads();
        // ---- stage K/V tile (fp32 -> bf16 hi/lo; V transposed) ----
#pragma unroll
        for (int it = 0; it < 2; it++) {
            int f4  = tid + it * 256;          // 0..511
            int key = f4 >> 3, d4 = f4 & 7;
            const float* base = qkv + (kb + key) * 384 + h * HD + d4 * 4;
            float4 kv = *reinterpret_cast<const float4*>(base + 128);
            float4 vv = *reinterpret_cast<const float4*>(base + 256);
            float kx[4] = {kv.x, kv.y, kv.z, kv.w};
            float vx[4] = {vv.x, vv.y, vv.z, vv.w};
            __nv_bfloat16 khb[4], klb[4], vhb[4], vlb[4];
#pragma unroll
            for (int j = 0; j < 4; j++) {
                bsplit(kx[j], khb[j], klb[j]);
                bsplit(vx[j], vhb[j], vlb[j]);
            }
            *reinterpret_cast<__nv_bfloat162*>(&Khi[key][d4 * 4])     = __halves2bfloat162(khb[0], khb[1]);
            *reinterpret_cast<__nv_bfloat162*>(&Khi[key][d4 * 4 + 2]) = __halves2bfloat162(khb[2], khb[3]);
            *reinterpret_cast<__nv_bfloat162*>(&Klo[key][d4 * 4])     = __halves2bfloat162(klb[0], klb[1]);
            *reinterpret_cast<__nv_bfloat162*>(&Klo[key][d4 * 4 + 2]) = __halves2bfloat162(klb[2], klb[3]);
#pragma unroll
            for (int j = 0; j < 4; j++) {
                Vthi[d4 * 4 + j][key] = vhb[j];
                Vtlo[d4 * 4 + j][key] = vlb[j];
            }
        }
        __syncthreads();

        // ---- QK^T: 8 n-tiles of 8 keys ----
        float Sf[8][4];
#pragma unroll
        for (int nt = 0; nt < 8; nt++) {
#pragma unroll
            for (int i = 0; i < 4; i++) Sf[nt][i] = 0.0f;
            int key = nt * 8 + g;
#pragma unroll
            for (int ks = 0; ks < 2; ks++) {
                uint32_t bh0 = *reinterpret_cast<const uint32_t*>(&Khi[key][ks * 16 + 2 * t4]);
                uint32_t bh1 = *reinterpret_cast<const uint32_t*>(&Khi[key][ks * 16 + 8 + 2 * t4]);
                uint32_t bl0 = *reinterpret_cast<const uint32_t*>(&Klo[key][ks * 16 + 2 * t4]);
                uint32_t bl1 = *reinterpret_cast<const uint32_t*>(&Klo[key][ks * 16 + 8 + 2 * t4]);
                mma16816(Sf[nt][0], Sf[nt][1], Sf[nt][2], Sf[nt][3],
                         Qhi[ks][0], Qhi[ks][1], Qhi[ks][2], Qhi[ks][3], bh0, bh1);
                mma16816(Sf[nt][0], Sf[nt][1], Sf[nt][2], Sf[nt][3],
                         Qlo[ks][0], Qlo[ks][1], Qlo[ks][2], Qlo[ks][3], bh0, bh1);
                mma16816(Sf[nt][0], Sf[nt][1], Sf[nt][2], Sf[nt][3],
                         Qhi[ks][0], Qhi[ks][1], Qhi[ks][2], Qhi[ks][3], bl0, bl1);
            }
        }

        // ---- mask ----
        if (kb + KT > sn) {
#pragma unroll
            for (int nt = 0; nt < 8; nt++) {
                int k0 = kb + nt * 8 + 2 * t4;
                if (k0     >= sn) { Sf[nt][0] = -INFINITY; Sf[nt][2] = -INFINITY; }
                if (k0 + 1 >= sn) { Sf[nt][1] = -INFINITY; Sf[nt][3] = -INFINITY; }
            }
        }

        // ---- online softmax ----
        float mx0 = -INFINITY, mx1 = -INFINITY;
#pragma unroll
        for (int nt = 0; nt < 8; nt++) {
            mx0 = fmaxf(mx0, fmaxf(Sf[nt][0], Sf[nt][1]));
            mx1 = fmaxf(mx1, fmaxf(Sf[nt][2], Sf[nt][3]));
        }
#pragma unroll
        for (int o = 1; o <= 2; o <<= 1) {
            mx0 = fmaxf(mx0, __shfl_xor_sync(0xffffffffu, mx0, o));
            mx1 = fmaxf(mx1, __shfl_xor_sync(0xffffffffu, mx1, o));
        }
        float mn0 = fmaxf(m0v, mx0);
        float mn1 = fmaxf(m1v, mx1);
        if (mn0 == -INFINITY) mn0 = 0.0f;   // fully-masked guard (consistent ref point)
        if (mn1 == -INFINITY) mn1 = 0.0f;
        float c0 = __expf(m0v - mn0);
        float c1 = __expf(m1v - mn1);
        l0v *= c0;  l1v *= c1;
#pragma unroll
        for (int nt = 0; nt < 4; nt++) {
            O[nt][0] *= c0; O[nt][1] *= c0;
            O[nt][2] *= c1; O[nt][3] *= c1;
        }
        m0v = mn0; m1v = mn1;

        float rs0 = 0.0f, rs1 = 0.0f;
        uint32_t Phi[4][4], Plo[4][4];
#pragma unroll
        for (int j = 0; j < 4; j++) {        // key-step j covers tiles 2j, 2j+1
#pragma unroll
            for (int tt = 0; tt < 2; tt++) {
                int nt = 2 * j + tt;
                float p0 = __expf(Sf[nt][0] - mn0);
                float p1 = __expf(Sf[nt][1] - mn0);
                float p2 = __expf(Sf[nt][2] - mn1);
                float p3 = __expf(Sf[nt][3] - mn1);
                rs0 += p0 + p1;
                rs1 += p2 + p3;
                packsplit2(p0, p1, Phi[j][tt * 2],     Plo[j][tt * 2]);
                packsplit2(p2, p3, Phi[j][tt * 2 + 1], Plo[j][tt * 2 + 1]);
            }
        }
#pragma unroll
        for (int o = 1; o <= 2; o <<= 1) {
            rs0 += __shfl_xor_sync(0xffffffffu, rs0, o);
            rs1 += __shfl_xor_sync(0xffffffffu, rs1, o);
        }
        l0v += rs0;  l1v += rs1;

        // ---- PV: 4 d-tiles x 4 key-steps ----
#pragma unroll
        for (int nt = 0; nt < 4; nt++) {
            int d = nt * 8 + g;
#pragma unroll
            for (int ks = 0; ks < 4; ks++) {
                uint32_t bh0 = *reinterpret_cast<const uint32_t*>(&Vthi[d][ks * 16 + 2 * t4]);
                uint32_t bh1 = *reinterpret_cast<const uint32_t*>(&Vthi[d][ks * 16 + 8 + 2 * t4]);
                uint32_t bl0 = *reinterpret_cast<const uint32_t*>(&Vtlo[d][ks * 16 + 2 * t4]);
                uint32_t bl1 = *reinterpret_cast<const uint32_t*>(&Vtlo[d][ks * 16 + 8 + 2 * t4]);
                mma16816(O[nt][0], O[nt][1], O[nt][2], O[nt][3],
                         Phi[ks][0], Phi[ks][1], Phi[ks][2], Phi[ks][3], bh0, bh1);
                mma16816(O[nt][0], O[nt][1], O[nt][2], O[nt][3],
                         Plo[ks][0], Plo[ks][1], Plo[ks][2], Plo[ks][3], bh0, bh1);
                mma16816(O[nt][0], O[nt][1], O[nt][2], O[nt][3],
                         Phi[ks][0], Phi[ks][1], Phi[ks][2], Phi[ks][3], bl0, bl1);
            }
        }
    }

    // ---- write partials (unnormalized) ----
    const int p0 = (h * NKC + kc) * S + r0;
    const int p1 = (h * NKC + kc) * S + r1;
    if (t4 == 0) {
        g_pm[p0] = m0v;  g_pl[p0] = l0v;
        g_pm[p1] = m1v;  g_pl[p1] = l1v;
    }
#pragma unroll
    for (int nt = 0; nt < 4; nt++) {
        int d = nt * 8 + 2 * t4;
        g_po[(size_t)p0 * HD + d]     = O[nt][0];
        g_po[(size_t)p0 * HD + d + 1] = O[nt][1];
        g_po[(size_t)p1 * HD + d]     = O[nt][2];
        g_po[(size_t)p1 * HD + d + 1] = O[nt][3];
    }
}

// ============================================================================
// K4b: split-K combine. grid = (S/128, 4 heads), 128 threads (1 query/thread)
// ============================================================================
__global__ void __launch_bounds__(128) k_attn_comb(void) {
    const int h = blockIdx.y;
    const int q = blockIdx.x * 128 + threadIdx.x;

    float M = -INFINITY;
#pragma unroll
    for (int kc = 0; kc < NKC; kc++)
        M = fmaxf(M, g_pm[(h * NKC + kc) * S + q]);

    float L = 0.0f;
    float o[HD];
#pragma unroll
    for (int d = 0; d < HD; d++) o[d] = 0.0f;

#pragma unroll
    for (int kc = 0; kc < NKC; kc++) {
        const int p = (h * NKC + kc) * S + q;
        float li = g_pl[p];
        if (li > 0.0f) {
            float w = __expf(g_pm[p] - M);
            L += li * w;
            const float4* po = reinterpret_cast<const float4*>(&g_po[(size_t)p * HD]);
#pragma unroll
            for (int d4 = 0; d4 < 8; d4++) {
                float4 v = po[d4];
                o[d4 * 4 + 0] = fmaf(w, v.x, o[d4 * 4 + 0]);
                o[d4 * 4 + 1] = fmaf(w, v.y, o[d4 * 4 + 1]);
                o[d4 * 4 + 2] = fmaf(w, v.z, o[d4 * 4 + 2]);
                o[d4 * 4 + 3] = fmaf(w, v.w, o[d4 * 4 + 3]);
            }
        }
    }

    float inv = (L > 0.0f) ? 1.0f / L : 0.0f;
#pragma unroll
    for (int d = 0; d < HD; d++)
        g_att[q * HID + h * HD + d] = o[d] * inv;
}

// ============================================================================
// masked row-sum of eig_filter (double accumulation)
// ============================================================================
__global__ void k_zero_xsum() {
    g_xsum[threadIdx.x] = 0.0;
}

__global__ void __launch_bounds__(128) k_rowsum(const int* __restrict__ snp) {
    const int sn  = *snp;
    const int tid = threadIdx.x;
    const int m0  = blockIdx.x * 128;
    double acc = 0.0;
    for (int r = 0; r < 128; r++) {
        int row = m0 + r;
        if (row < sn) acc += (double)g_eigf[row * HID + tid];
    }
    atomicAdd(&g_xsum[tid], acc);
}

// ============================================================================
// pooled coefficients (single block)
// ============================================================================
__global__ void __launch_bounds__(128) k_pool(const float* __restrict__ dscW, const float* __restrict__ dscb,
                                              const float* __restrict__ dwvW, const float* __restrict__ dwvb,
                                              const float* __restrict__ dssW, const float* __restrict__ dssb,
                                              const int* __restrict__ lenp, const int* __restrict__ snp) {
    const int tid = threadIdx.x;
    __shared__ float sig[104];
    __shared__ float ssum[2];
    const float lenf = (float)(*lenp);
    const float snf  = (float)(*snp);

    if (tid < 104) {
        const float* W; const float* bb; int c; int NCc;
        if (tid < 50)       { W = dscW; bb = dscb; c = tid;       NCc = NCOE; }
        else if (tid < 100) { W = dwvW; bb = dwvb; c = tid - 50;  NCc = NCOE; }
        else                { W = dssW; bb = dssb; c = tid - 100; NCc = NSCALES; }
        double acc = 0.0;
        for (int k = 0; k < HID; k++) acc += g_xsum[k] * (double)W[k * NCc + c];
        float pooled = (float)((acc + (double)(snf * bb[c])) / (double)(lenf + 1e-8f));
        sig[tid] = 1.0f / (1.0f + expf(-pooled));
    }
    __syncthreads();
    if (tid == 0) { float t = 0.f; for (int i = 0;  i < 50;  i++) t += sig[i]; ssum[0] = t; }
    if (tid == 1) { float t = 0.f; for (int i = 50; i < 100; i++) t += sig[i]; ssum[1] = t; }
    __syncthreads();
    if (tid < 50)       g_coef[tid] = sig[tid] / (ssum[0] + 1e-8f);
    else if (tid < 100) g_coef[tid] = sig[tid] / (ssum[1] + 1e-8f);
    else if (tid < 104) g_coef[tid] = sig[tid] * 5.0f;   // THRE
}

// ============================================================================
// Chebyshev synthesis + L2 normalize  ->  out[S, 5]
// ============================================================================
__global__ void __launch_bounds__(128) k_final(const float* __restrict__ eve,
                                               float* __restrict__ out) {
    __shared__ float cs[NCOE], cw[NCOE], sc[NSCALES];
    const int tid = threadIdx.x;
    if (tid < 50)        cs[tid]       = g_coef[tid];
    else if (tid < 100)  cw[tid - 50]  = g_coef[tid];
    else if (tid < 104)  sc[tid - 100] = g_coef[tid];
    __syncthreads();

    const int s = blockIdx.x * 128 + tid;
    const float e = eve[s];
    float vals[5];

    {   // scaling channel: y = e - 1; coefficients on T_1,T_3,...
        float y  = e - 1.0f;
        float te = 1.0f, to = y;
        float acc = cs[0] * (0.5f * (1.0f - to));
#pragma unroll
        for (int c = 1; c < NCOE; c++) {
            te = 2.0f * y * to - te;          // T_{2c}
            to = 2.0f * y * te - to;          // T_{2c+1}
            acc += cs[c] * (0.5f * (1.0f - to));
        }
        vals[0] = acc;
    }

#pragma unroll
    for (int j = 0; j < NSCALES; j++) {       // wavelet channels: T_0,T_2,...
        float f = e * sc[j];
        if (f > 2.0f) f = 0.0f;
        float y  = f - 1.0f;
        float te = 1.0f, to = y;
        float acc = 0.0f;                      // cw[0] * 0.5*(1-T_0) = 0
#pragma unroll
        for (int c = 1; c < NCOE; c++) {
            te = 2.0f * y * to - te;          // T_{2c}
            acc += cw[c] * (0.5f * (1.0f - te));
            to = 2.0f * y * te - to;          // T_{2c+1}
        }
        vals[1 + j] = acc;
    }

    float n2 = 0.0f;
#pragma unroll
    for (int i = 0; i < 5; i++) n2 += vals[i] * vals[i];
    float inv = 1.0f / (sqrtf(n2) + 1e-8f);
#pragma unroll
    for (int i = 0; i < 5; i++) out[s * 5 + i] = vals[i] * inv;
}

// ============================================================================
// launch
// ============================================================================
extern "C" void kernel_launch(void* const* d_in, const int* in_sizes, int n_in,
                              void* d_out, int out_size) {
    const float* eve      = (const float*)d_in[0];
    const int*   lenp     = (const int*)  d_in[1];
    const int*   snp      = (const int*)  d_in[2];
    const float* eig_w_W  = (const float*)d_in[3];
    const float* eig_w_b  = (const float*)d_in[4];
    const float* mha_ln_g = (const float*)d_in[5];
    const float* mha_ln_b = (const float*)d_in[6];
    const float* in_W     = (const float*)d_in[7];
    const float* in_b     = (const float*)d_in[8];
    const float* out_W    = (const float*)d_in[9];
    const float* out_b    = (const float*)d_in[10];
    const float* ffn_ln_g = (const float*)d_in[11];
    const float* ffn_ln_b = (const float*)d_in[12];
    const float* ffn1_W   = (const float*)d_in[13];
    const float* ffn1_b   = (const float*)d_in[14];
    const float* ffn2_W   = (const float*)d_in[15];
    const float* ffn2_b   = (const float*)d_in[16];
    const float* dsc_W    = (const float*)d_in[17];
    const float* dsc_b    = (const float*)d_in[18];
    const float* dwv_W    = (const float*)d_in[19];
    const float* dwv_b    = (const float*)d_in[20];
    const float* dss_W    = (const float*)d_in[21];
    const float* dss_b    = (const float*)d_in[22];
    float* out = (float*)d_out;

    float *p_eig, *p_qkv, *p_att, *p_h1, *p_eigf;
    cudaGetSymbolAddress((void**)&p_eig,  g_eig);
    cudaGetSymbolAddress((void**)&p_qkv,  g_qkv);
    cudaGetSymbolAddress((void**)&p_att,  g_att);
    cudaGetSymbolAddress((void**)&p_h1,   g_h1);
    cudaGetSymbolAddress((void**)&p_eigf, g_eigf);

    // 1) eig = sine_encoding(eve) @ W + b
    k_sine_enc<<<S / 16, 128>>>(eve, eig_w_W, eig_w_b);
    // 2) qkv = LN(eig) @ in_W + in_b        (LN fused)
    k_gemm<3, 0, 0, 1><<<S / 16, 128>>>(p_eig, in_W, in_b, nullptr, p_qkv, mha_ln_g, mha_ln_b);
    // 3) attention (tensor-core split-K partials + combine)
    k_attn_mma<<<dim3(S / QT, NHEADS, NKC), 256>>>(p_qkv, snp);
    k_attn_comb<<<dim3(S / 128, NHEADS), 128>>>();
    // 4) eig = eig + att @ out_W + out_b
    k_gemm<1, 0, 1, 0><<<S / 16, 128>>>(p_att, out_W, out_b, p_eig, p_eig, nullptr, nullptr);
    // 5) h1 = gelu(LN(eig) @ ffn1_W + b)    (LN fused)
    k_gemm<1, 1, 0, 1><<<S / 16, 128>>>(p_eig, ffn1_W, ffn1_b, nullptr, p_h1, ffn_ln_g, ffn_ln_b);
    // 6) eigf = eig + h1 @ ffn2_W + b
    k_gemm<1, 0, 1, 0><<<S / 16, 128>>>(p_h1, ffn2_W, ffn2_b, p_eig, p_eigf, nullptr, nullptr);
    // 7) masked row-sum (double)
    k_zero_xsum<<<1, 128>>>();
    k_rowsum<<<S / 128, 128>>>(snp);
    // 8) pooled coefficients
    k_pool<<<1, 128>>>(dsc_W, dsc_b, dwv_W, dwv_b, dss_W, dss_b, lenp, snp);
    // 9) Chebyshev synthesis + normalize
    k_final<<<S / 128, 128>>>(eve, out);
}